// round 1
// baseline (speedup 1.0000x reference)
#include <cuda_runtime.h>
#include <cuda_bf16.h>
#include <math.h>

// LandmarkLoss: B=16, N=4096, flow [B,2,W,H] with W=H=1024.
// loss = sum over valid points of (x1+o0-x2)^2 + (y1+o1-y2)^2, / (2B)
// with the reference's EXACT (non-standard) bilinear weights:
//   wa = (x1-x1d)*(y1-y1d)
//   wb = (x1u-x1)*(y1u-x1)   <- uses x1, faithful to source
//   wc = (x1u-x1)*(y1-y1d)
//   wd = (x1-x1d)*(y1u-x1)   <- uses x1, faithful to source

#define LB 16
#define LN 4096
#define LW 1024
#define LH 1024

__global__ void ll_init_out(float* out) { out[0] = 0.0f; }

__global__ __launch_bounds__(256) void ll_loss_kernel(
    const float* __restrict__ lm,     // [B,N,4]
    const float* __restrict__ flow,   // [B,2,W,H]
    float* __restrict__ out)
{
    int i = blockIdx.x * blockDim.x + threadIdx.x;
    float acc = 0.0f;

    if (i < LB * LN) {
        int b = i >> 12;  // / LN
        float4 l = reinterpret_cast<const float4*>(lm)[i];
        float x1 = l.x, y1 = l.y, x2 = l.z, y2 = l.w;

        float x1d = floorf(x1);
        float y1d = floorf(y1);
        float x1u = x1d + 1.0f;
        float y1u = y1d + 1.0f;

        bool valid = (x1u < (float)LW) && (y1u < (float)LH);

        int xd = (int)x1d; xd = max(0, min(xd, LW - 2));
        int yd = (int)y1d; yd = max(0, min(yd, LH - 2));

        const float* f0 = flow + (size_t)b * (2 * LW * LH); // channel 0
        const float* f1 = f0 + (LW * LH);                   // channel 1

        int idx_dd = xd * LH + yd;    // (xd, yd)
        int idx_du = idx_dd + 1;      // (xd, yu)
        int idx_ud = idx_dd + LH;     // (xu, yd)
        int idx_uu = idx_ud + 1;      // (xu, yu)

        // Issue all 8 gathers up-front for maximum MLP.
        float a0 = __ldg(f0 + idx_dd);
        float b0 = __ldg(f0 + idx_uu);
        float c0 = __ldg(f0 + idx_ud);
        float d0 = __ldg(f0 + idx_du);
        float a1 = __ldg(f1 + idx_dd);
        float b1 = __ldg(f1 + idx_uu);
        float c1 = __ldg(f1 + idx_ud);
        float d1 = __ldg(f1 + idx_du);

        float wa = (x1 - x1d) * (y1 - y1d);
        float wb = (x1u - x1) * (y1u - x1);  // faithful to source
        float wc = (x1u - x1) * (y1 - y1d);
        float wd = (x1 - x1d) * (y1u - x1);  // faithful to source

        float o0 = a0 * wa + b0 * wb + c0 * wc + d0 * wd;
        float o1 = a1 * wa + b1 * wb + c1 * wc + d1 * wd;

        float dx = x1 + o0 - x2;
        float dy = y1 + o1 - y2;
        float pp = dx * dx + dy * dy;
        acc = valid ? pp : 0.0f;
    }

    // Warp reduce
    #pragma unroll
    for (int o = 16; o > 0; o >>= 1)
        acc += __shfl_down_sync(0xFFFFFFFFu, acc, o);

    __shared__ float s[8];
    int lane = threadIdx.x & 31;
    int wid  = threadIdx.x >> 5;
    if (lane == 0) s[wid] = acc;
    __syncthreads();

    if (wid == 0) {
        acc = (lane < 8) ? s[lane] : 0.0f;
        #pragma unroll
        for (int o = 4; o > 0; o >>= 1)
            acc += __shfl_down_sync(0xFFFFFFFFu, acc, o);
        if (lane == 0)
            atomicAdd(out, acc * (1.0f / (2.0f * (float)LB)));
    }
}

extern "C" void kernel_launch(void* const* d_in, const int* in_sizes, int n_in,
                              void* d_out, int out_size)
{
    const float* lm   = (const float*)d_in[0];  // landmarks [B,N,4]
    const float* flow = (const float*)d_in[1];  // flow [B,2,W,H]
    float* out = (float*)d_out;

    ll_init_out<<<1, 1>>>(out);
    int total = LB * LN;
    int threads = 256;
    int blocks = (total + threads - 1) / threads;
    ll_loss_kernel<<<blocks, threads>>>(lm, flow, out);
}